// round 2
// baseline (speedup 1.0000x reference)
#include <cuda_runtime.h>
#include <math.h>

#define N_NODES 100000
#define N_EDGES_MAX 1300000
#define IN_DIM 256
#define HID 64

// ---------------- scratch (static device globals: no allocation allowed) ----------------
__device__ int    g_counts[N_NODES];
__device__ int    g_offsets[N_NODES];
__device__ int    g_cursor[N_NODES];
__device__ float2 g_edge[N_EDGES_MAX];         // permuted (col_as_int_bits, val) pairs
__device__ int    g_blocksums[128];
__device__ float  g_H[(size_t)N_NODES * HID];  // GEMM output buffer
__device__ float  g_Z[(size_t)N_NODES * HID];  // activated layer-1 output

// ---------------- CSR build: counting sort of edges by destination row ----------------
__global__ void hist_kernel(const int* __restrict__ rows, int E) {
    int i = blockIdx.x * blockDim.x + threadIdx.x;
    if (i < E) atomicAdd(&g_counts[rows[i]], 1);
}

__global__ void scan_block_kernel() {
    __shared__ int sh[1024];
    int i = blockIdx.x * 1024 + threadIdx.x;
    int v = (i < N_NODES) ? g_counts[i] : 0;
    sh[threadIdx.x] = v;
    __syncthreads();
    #pragma unroll
    for (int d = 1; d < 1024; d <<= 1) {
        int t = 0;
        if ((int)threadIdx.x >= d) t = sh[threadIdx.x - d];
        __syncthreads();
        if ((int)threadIdx.x >= d) sh[threadIdx.x] += t;
        __syncthreads();
    }
    if (i < N_NODES) g_offsets[i] = sh[threadIdx.x] - v;   // exclusive within block
    if (threadIdx.x == 1023) g_blocksums[blockIdx.x] = sh[1023];
}

__global__ void scan_sums_kernel(int nb) {
    if (blockIdx.x == 0 && threadIdx.x == 0) {
        int acc = 0;
        for (int b = 0; b < nb; b++) { int t = g_blocksums[b]; g_blocksums[b] = acc; acc += t; }
    }
}

__global__ void add_sums_kernel() {
    int i = blockIdx.x * 1024 + threadIdx.x;
    if (i < N_NODES) {
        int o = g_offsets[i] + g_blocksums[blockIdx.x];
        g_offsets[i] = o;
        g_cursor[i]  = o;
    }
}

// Scatter the edge PAYLOAD (col, val) directly into CSR order — the SPMM then
// needs one 8-byte broadcast load per edge instead of perm->col/val chains.
__global__ void scatter_kernel(const int* __restrict__ rows, const int* __restrict__ cols,
                               const float* __restrict__ vals, int E) {
    int i = blockIdx.x * blockDim.x + threadIdx.x;
    if (i < E) {
        int p = atomicAdd(&g_cursor[rows[i]], 1);
        g_edge[p] = make_float2(__int_as_float(cols[i]), vals[i]);
    }
}

// ---------------- dense GEMM: C[M,64] = A[M,lda] @ B[K,64] ----------------
// block tile 128x64, 256 threads, 8x4 micro-tile per thread, KC=32 shared chunks.
__global__ __launch_bounds__(256) void gemm_kernel(
    const float* __restrict__ A, int lda,
    const float* __restrict__ B, int K,
    float* __restrict__ C)
{
    __shared__ float As[32][132];   // [k][row], pad 132 to spread banks
    __shared__ float Bs[32][64];    // [k][col]

    const int t  = threadIdx.x;
    const int r0 = (t >> 4) * 8;    // 0..120
    const int c0 = (t & 15) * 4;    // 0..60
    const int blockRow = blockIdx.x * 128;

    float acc[8][4];
    #pragma unroll
    for (int i = 0; i < 8; i++)
        #pragma unroll
        for (int j = 0; j < 4; j++) acc[i][j] = 0.f;

    for (int kc = 0; kc < K; kc += 32) {
        // load A chunk: 128 rows x 32 k = 1024 float4; 4 per thread
        #pragma unroll
        for (int i = 0; i < 4; i++) {
            int idx4 = t + i * 256;
            int k4 = idx4 & 7;
            int ar = idx4 >> 3;
            int gr = blockRow + ar;
            float4 v = make_float4(0.f, 0.f, 0.f, 0.f);
            if (gr < N_NODES) v = *(const float4*)(A + gr * lda + kc + k4 * 4);
            As[k4 * 4 + 0][ar] = v.x;
            As[k4 * 4 + 1][ar] = v.y;
            As[k4 * 4 + 2][ar] = v.z;
            As[k4 * 4 + 3][ar] = v.w;
        }
        // load B chunk: 32 x 64 = 512 float4; 2 per thread
        #pragma unroll
        for (int i = 0; i < 2; i++) {
            int idx4 = t + i * 256;
            int n4 = idx4 & 15;
            int bk = idx4 >> 4;
            *(float4*)&Bs[bk][n4 * 4] = *(const float4*)(B + (kc + bk) * 64 + n4 * 4);
        }
        __syncthreads();

        #pragma unroll
        for (int k = 0; k < 32; k++) {
            float a[8], b[4];
            *(float4*)(a)     = *(const float4*)&As[k][r0];
            *(float4*)(a + 4) = *(const float4*)&As[k][r0 + 4];
            *(float4*)(b)     = *(const float4*)&Bs[k][c0];
            #pragma unroll
            for (int i = 0; i < 8; i++)
                #pragma unroll
                for (int j = 0; j < 4; j++)
                    acc[i][j] = fmaf(a[i], b[j], acc[i][j]);
        }
        __syncthreads();
    }

    #pragma unroll
    for (int i = 0; i < 8; i++) {
        int gr = blockRow + r0 + i;
        if (gr < N_NODES)
            *(float4*)(C + gr * 64 + c0) =
                make_float4(acc[i][0], acc[i][1], acc[i][2], acc[i][3]);
    }
}

// ---------------- SPMM (CSR gather, warp per row) + fused epilogue ----------------
// mode 0: out = selu(acc + bias)
// mode 1: out = L2-normalize(acc + bias)
__global__ void spmm_kernel(const float* __restrict__ Hin, const float* __restrict__ bias,
                            float* __restrict__ outp, int mode)
{
    int w    = (blockIdx.x * blockDim.x + threadIdx.x) >> 5;
    int lane = threadIdx.x & 31;
    if (w >= N_NODES) return;

    int start = g_offsets[w];
    int cnt   = g_counts[w];

    const float2* __restrict__ H2 = (const float2*)Hin;
    float2 bv = ((const float2*)bias)[lane];
    float ax = bv.x, ay = bv.y;

    int j = 0;
    // unroll-4: front-batch edge loads + 4 independent H gathers in flight
    for (; j + 4 <= cnt; j += 4) {
        float2 e0 = g_edge[start + j + 0];
        float2 e1 = g_edge[start + j + 1];
        float2 e2 = g_edge[start + j + 2];
        float2 e3 = g_edge[start + j + 3];
        int c0 = __float_as_int(e0.x), c1 = __float_as_int(e1.x);
        int c2 = __float_as_int(e2.x), c3 = __float_as_int(e3.x);
        float2 h0 = H2[c0 * 32 + lane];
        float2 h1 = H2[c1 * 32 + lane];
        float2 h2 = H2[c2 * 32 + lane];
        float2 h3 = H2[c3 * 32 + lane];
        ax = fmaf(e0.y, h0.x, ax);  ay = fmaf(e0.y, h0.y, ay);
        ax = fmaf(e1.y, h1.x, ax);  ay = fmaf(e1.y, h1.y, ay);
        ax = fmaf(e2.y, h2.x, ax);  ay = fmaf(e2.y, h2.y, ay);
        ax = fmaf(e3.y, h3.x, ax);  ay = fmaf(e3.y, h3.y, ay);
    }
    for (; j < cnt; j++) {
        float2 e = g_edge[start + j];
        float2 h = H2[__float_as_int(e.x) * 32 + lane];
        ax = fmaf(e.y, h.x, ax);
        ay = fmaf(e.y, h.y, ay);
    }

    if (mode == 0) {
        const float sc = 1.0507009873554805f;
        const float al = 1.6732632423543772f;
        float rx = ax > 0.f ? sc * ax : sc * al * (expf(ax) - 1.f);
        float ry = ay > 0.f ? sc * ay : sc * al * (expf(ay) - 1.f);
        ((float2*)outp)[w * 32 + lane] = make_float2(rx, ry);
    } else {
        float ss = ax * ax + ay * ay;
        #pragma unroll
        for (int o = 16; o > 0; o >>= 1) ss += __shfl_xor_sync(0xffffffffu, ss, o);
        float inv = 1.f / fmaxf(sqrtf(ss), 1e-12f);
        ((float2*)outp)[w * 32 + lane] = make_float2(ax * inv, ay * inv);
    }
}

// ---------------- launcher ----------------
extern "C" void kernel_launch(void* const* d_in, const int* in_sizes, int n_in,
                              void* d_out, int out_size)
{
    const float* X1    = (const float*)d_in[0];
    const float* X2    = (const float*)d_in[1];
    const int*   rows1 = (const int*)  d_in[2];
    const int*   cols1 = (const int*)  d_in[3];
    const float* vals1 = (const float*)d_in[4];
    const int*   rows2 = (const int*)  d_in[5];
    const int*   cols2 = (const int*)  d_in[6];
    const float* vals2 = (const float*)d_in[7];
    const float* W1    = (const float*)d_in[8];
    const float* b1    = (const float*)d_in[9];
    const float* W2    = (const float*)d_in[10];
    const float* b2    = (const float*)d_in[11];
    float* out = (float*)d_out;
    const int E = in_sizes[2];

    float *Hp = nullptr, *Zp = nullptr;
    int   *Cp = nullptr;
    cudaGetSymbolAddress((void**)&Hp, g_H);
    cudaGetSymbolAddress((void**)&Zp, g_Z);
    cudaGetSymbolAddress((void**)&Cp, g_counts);

    const int scanBlocks = (N_NODES + 1023) / 1024;

    for (int g = 0; g < 2; g++) {
        const float* X    = g ? X2    : X1;
        const int*   rows = g ? rows2 : rows1;
        const int*   cols = g ? cols2 : cols1;
        const float* vals = g ? vals2 : vals1;
        float* outg = out + (size_t)g * N_NODES * HID;

        // CSR build (shared by both SPMM layers of this graph)
        cudaMemsetAsync(Cp, 0, N_NODES * sizeof(int));
        hist_kernel<<<(E + 255) / 256, 256>>>(rows, E);
        scan_block_kernel<<<scanBlocks, 1024>>>();
        scan_sums_kernel<<<1, 32>>>(scanBlocks);
        add_sums_kernel<<<scanBlocks, 1024>>>();
        scatter_kernel<<<(E + 255) / 256, 256>>>(rows, cols, vals, E);

        // layer 1: H = X @ W1 ; Z = selu(A @ H + b1)
        gemm_kernel<<<(N_NODES + 127) / 128, 256>>>(X, IN_DIM, W1, IN_DIM, Hp);
        spmm_kernel<<<(N_NODES * 32 + 255) / 256, 256>>>(Hp, b1, Zp, 0);

        // layer 2: H = Z @ W2 ; out = l2norm(A @ H + b2)
        gemm_kernel<<<(N_NODES + 127) / 128, 256>>>(Zp, HID, W2, HID, Hp);
        spmm_kernel<<<(N_NODES * 32 + 255) / 256, 256>>>(Hp, b2, outg, 1);
    }
}

// round 6
// speedup vs baseline: 1.0057x; 1.0057x over previous
#include <cuda_runtime.h>
#include <math.h>

#define N_NODES 100000
#define N_TOT   200000            // both graphs fused
#define N_EDGES_MAX 1300000
#define IN_DIM 256
#define HID 64
#define SCAN_BLOCKS ((N_TOT + 1023) / 1024)   // 196
#define TM 256                    // GEMM block-tile rows
#define KC 16                     // GEMM k-chunk

// ---------------- packed f32x2 helpers (Blackwell dual-pumped fp32 FMA) ----------------
typedef unsigned long long f32x2_t;

__device__ __forceinline__ f32x2_t ffma2(f32x2_t a, f32x2_t b, f32x2_t c) {
    f32x2_t d;
    asm("fma.rn.f32x2 %0, %1, %2, %3;" : "=l"(d) : "l"(a), "l"(b), "l"(c));
    return d;
}
__device__ __forceinline__ f32x2_t dup2(float x) {
    f32x2_t d;
    asm("mov.b64 %0, {%1, %1};" : "=l"(d) : "f"(x));
    return d;
}
__device__ __forceinline__ float2 unpack2(f32x2_t d) {
    float2 r;
    asm("mov.b64 {%0, %1}, %2;" : "=f"(r.x), "=f"(r.y) : "l"(d));
    return r;
}

// ---------------- scratch (static device globals: no allocation allowed) ----------------
__device__ int    g_counts[N_TOT];
__device__ int    g_offsets[N_TOT];
__device__ int    g_cursor[N_TOT];
__device__ float2 g_edge[2 * N_EDGES_MAX];     // CSR-ordered (globalized col, val)
__device__ int    g_blocksums[256];
__device__ float  g_H[(size_t)N_TOT * HID];    // GEMM output buffer (both graphs)
__device__ float  g_Z[(size_t)N_TOT * HID];    // activated layer-1 output (both graphs)

// ---------------- CSR build: counting sort of edges by destination row ----------------
__global__ void hist_kernel(const int* __restrict__ rows1, const int* __restrict__ rows2, int E) {
    int i = blockIdx.x * blockDim.x + threadIdx.x;
    if (i < 2 * E) {
        int r = (i < E) ? rows1[i] : (N_NODES + rows2[i - E]);
        atomicAdd(&g_counts[r], 1);
    }
}

__global__ void scan_block_kernel() {
    __shared__ int sh[1024];
    int i = blockIdx.x * 1024 + threadIdx.x;
    int v = (i < N_TOT) ? g_counts[i] : 0;
    sh[threadIdx.x] = v;
    __syncthreads();
    #pragma unroll
    for (int d = 1; d < 1024; d <<= 1) {
        int t = 0;
        if ((int)threadIdx.x >= d) t = sh[threadIdx.x - d];
        __syncthreads();
        if ((int)threadIdx.x >= d) sh[threadIdx.x] += t;
        __syncthreads();
    }
    if (i < N_TOT) g_offsets[i] = sh[threadIdx.x] - v;   // exclusive within block
    if (threadIdx.x == 1023) g_blocksums[blockIdx.x] = sh[1023];
}

// Fused: per-block parallel reduction of predecessor block sums + offset fixup.
__global__ void add_sums_kernel() {
    __shared__ int sh[1024];
    int b = blockIdx.x;
    sh[threadIdx.x] = ((int)threadIdx.x < b) ? g_blocksums[threadIdx.x] : 0;  // b <= 195 < 1024
    __syncthreads();
    #pragma unroll
    for (int d = 512; d > 0; d >>= 1) {
        if ((int)threadIdx.x < d) sh[threadIdx.x] += sh[threadIdx.x + d];
        __syncthreads();
    }
    int base = sh[0];
    int i = b * 1024 + threadIdx.x;
    if (i < N_TOT) {
        int o = g_offsets[i] + base;
        g_offsets[i] = o;
        g_cursor[i]  = o;
    }
}

// Scatter edge PAYLOAD (globalized col, val) into CSR order.
__global__ void scatter_kernel(const int* __restrict__ rows1, const int* __restrict__ cols1,
                               const float* __restrict__ vals1,
                               const int* __restrict__ rows2, const int* __restrict__ cols2,
                               const float* __restrict__ vals2, int E) {
    int i = blockIdx.x * blockDim.x + threadIdx.x;
    if (i >= 2 * E) return;
    int r, c; float v;
    if (i < E) { r = rows1[i];            c = cols1[i];            v = vals1[i]; }
    else       { int j = i - E;
                 r = N_NODES + rows2[j];  c = N_NODES + cols2[j];  v = vals2[j]; }
    int p = atomicAdd(&g_cursor[r], 1);
    g_edge[p] = make_float2(__int_as_float(c), v);
}

// ---------------- dense GEMM: C[M,64] = A[M,lda] @ B[K,64], M split across A0/A1 ----------------
// 256x64 block tile, 256 threads, 8x8 micro-tile as 4 row-pairs x 8 cols in packed
// f32x2 accumulators (fma.rn.f32x2 = dual-pumped fp32 FMA), KC=16 register-prefetch pipeline.
// Pass Mhalf >= N_TOT for a contiguous A.
__global__ __launch_bounds__(256, 2) void gemm_kernel(
    const float* __restrict__ A0, const float* __restrict__ A1, int Mhalf,
    int lda, const float* __restrict__ B, int K,
    float* __restrict__ C)
{
    __shared__ float As[KC][TM + 4];   // [k][row], pad 4; row stride 1040B (8B-aligned)
    __shared__ float Bs[KC][64];       // [k][col]

    const int t  = threadIdx.x;
    const int r0 = (t >> 3) * 8;       // 0..248, thread's 8 rows
    const int c0 = (t & 7) * 8;        // 0..56, thread's 8 cols
    const int blockRow = blockIdx.x * TM;

    // A fragment sources: 256 rows x 16 k = 1024 float4, 4 per thread.
    const float* srcA[4];
    int rowA[4], k4A[4];
    #pragma unroll
    for (int i = 0; i < 4; i++) {
        int idx4 = t + i * 256;
        int row = idx4 >> 2, k4 = idx4 & 3;
        rowA[i] = row; k4A[i] = k4;
        int gr = blockRow + row;
        if (gr > N_TOT - 1) gr = N_TOT - 1;          // clamp; stores are masked
        const float* base = (gr < Mhalf) ? (A0 + (size_t)gr * lda)
                                         : (A1 + (size_t)(gr - Mhalf) * lda);
        srcA[i] = base + k4 * 4;
    }
    // B fragment source: 16 x 64 = 256 float4, 1 per thread
    const int bkB = t >> 4, n4B = t & 15;
    const float* srcB = B + bkB * 64 + n4B * 4;

    f32x2_t acc[4][8];
    #pragma unroll
    for (int i = 0; i < 4; i++)
        #pragma unroll
        for (int j = 0; j < 8; j++) acc[i][j] = 0ull;  // (0.f, 0.f)

    const int nch = K / KC;
    float4 rA[4], rB;

    #pragma unroll
    for (int i = 0; i < 4; i++) rA[i] = *(const float4*)(srcA[i]);
    rB = *(const float4*)(srcB);

    for (int kc = 0; kc < nch; kc++) {
        // commit current chunk to shared ([k][row] transpose for A)
        #pragma unroll
        for (int i = 0; i < 4; i++) {
            As[k4A[i] * 4 + 0][rowA[i]] = rA[i].x;
            As[k4A[i] * 4 + 1][rowA[i]] = rA[i].y;
            As[k4A[i] * 4 + 2][rowA[i]] = rA[i].z;
            As[k4A[i] * 4 + 3][rowA[i]] = rA[i].w;
        }
        *(float4*)&Bs[bkB][n4B * 4] = rB;
        __syncthreads();

        // prefetch next chunk (latency hidden behind the FMA block)
        if (kc + 1 < nch) {
            int off = (kc + 1) * KC;
            #pragma unroll
            for (int i = 0; i < 4; i++) rA[i] = *(const float4*)(srcA[i] + off);
            rB = *(const float4*)(srcB + off * 64);
        }

        #pragma unroll
        for (int k = 0; k < KC; k++) {
            // 4 row-pairs load directly as packed f32x2 (LDS.64, broadcast-friendly)
            f32x2_t a0 = *(const f32x2_t*)&As[k][r0];
            f32x2_t a1 = *(const f32x2_t*)&As[k][r0 + 2];
            f32x2_t a2 = *(const f32x2_t*)&As[k][r0 + 4];
            f32x2_t a3 = *(const f32x2_t*)&As[k][r0 + 6];
            float4 bl = *(const float4*)&Bs[k][c0];
            float4 bh = *(const float4*)&Bs[k][c0 + 4];
            float bv[8] = {bl.x, bl.y, bl.z, bl.w, bh.x, bh.y, bh.z, bh.w};
            #pragma unroll
            for (int j = 0; j < 8; j++) {
                f32x2_t bd = dup2(bv[j]);
                acc[0][j] = ffma2(a0, bd, acc[0][j]);
                acc[1][j] = ffma2(a1, bd, acc[1][j]);
                acc[2][j] = ffma2(a2, bd, acc[2][j]);
                acc[3][j] = ffma2(a3, bd, acc[3][j]);
            }
        }
        __syncthreads();
    }

    // epilogue: unpack row-pairs and store 2 float4 per row
    #pragma unroll
    for (int i = 0; i < 4; i++) {
        int gr = blockRow + r0 + 2 * i;
        float2 u[8];
        #pragma unroll
        for (int j = 0; j < 8; j++) u[j] = unpack2(acc[i][j]);
        if (gr < N_TOT) {
            *(float4*)(C + (size_t)gr * 64 + c0)     = make_float4(u[0].x, u[1].x, u[2].x, u[3].x);
            *(float4*)(C + (size_t)gr * 64 + c0 + 4) = make_float4(u[4].x, u[5].x, u[6].x, u[7].x);
        }
        if (gr + 1 < N_TOT) {
            *(float4*)(C + (size_t)(gr + 1) * 64 + c0)     = make_float4(u[0].y, u[1].y, u[2].y, u[3].y);
            *(float4*)(C + (size_t)(gr + 1) * 64 + c0 + 4) = make_float4(u[4].y, u[5].y, u[6].y, u[7].y);
        }
    }
}

// ---------------- SPMM (CSR gather, warp per row) + fused epilogue ----------------
// mode 0: out = selu(acc + bias)   mode 1: out = L2-normalize(acc + bias)
__global__ void spmm_kernel(const float* __restrict__ Hin, const float* __restrict__ bias,
                            float* __restrict__ outp, int mode)
{
    int w    = (blockIdx.x * blockDim.x + threadIdx.x) >> 5;
    int lane = threadIdx.x & 31;
    if (w >= N_TOT) return;

    int start = g_offsets[w];
    int cnt   = g_counts[w];

    const float2* __restrict__ H2 = (const float2*)Hin;
    float2 bv = ((const float2*)bias)[lane];
    float ax = bv.x, ay = bv.y;

    int j = 0;
    for (; j + 4 <= cnt; j += 4) {           // front-batched: 4 H gathers in flight
        float2 e0 = g_edge[start + j + 0];
        float2 e1 = g_edge[start + j + 1];
        float2 e2 = g_edge[start + j + 2];
        float2 e3 = g_edge[start + j + 3];
        int c0 = __float_as_int(e0.x), c1 = __float_as_int(e1.x);
        int c2 = __float_as_int(e2.x), c3 = __float_as_int(e3.x);
        float2 h0 = H2[(size_t)c0 * 32 + lane];
        float2 h1 = H2[(size_t)c1 * 32 + lane];
        float2 h2 = H2[(size_t)c2 * 32 + lane];
        float2 h3 = H2[(size_t)c3 * 32 + lane];
        ax = fmaf(e0.y, h0.x, ax);  ay = fmaf(e0.y, h0.y, ay);
        ax = fmaf(e1.y, h1.x, ax);  ay = fmaf(e1.y, h1.y, ay);
        ax = fmaf(e2.y, h2.x, ax);  ay = fmaf(e2.y, h2.y, ay);
        ax = fmaf(e3.y, h3.x, ax);  ay = fmaf(e3.y, h3.y, ay);
    }
    for (; j < cnt; j++) {
        float2 e = g_edge[start + j];
        float2 h = H2[(size_t)__float_as_int(e.x) * 32 + lane];
        ax = fmaf(e.y, h.x, ax);
        ay = fmaf(e.y, h.y, ay);
    }

    if (mode == 0) {
        const float sc = 1.0507009873554805f;
        const float al = 1.6732632423543772f;
        float rx = ax > 0.f ? sc * ax : sc * al * (expf(ax) - 1.f);
        float ry = ay > 0.f ? sc * ay : sc * al * (expf(ay) - 1.f);
        ((float2*)outp)[(size_t)w * 32 + lane] = make_float2(rx, ry);
    } else {
        float ss = ax * ax + ay * ay;
        #pragma unroll
        for (int o = 16; o > 0; o >>= 1) ss += __shfl_xor_sync(0xffffffffu, ss, o);
        float inv = 1.f / fmaxf(sqrtf(ss), 1e-12f);
        ((float2*)outp)[(size_t)w * 32 + lane] = make_float2(ax * inv, ay * inv);
    }
}

// ---------------- launcher ----------------
// scatter is placed AFTER gemm1 (only spmm depends on it) to steer the fixed
// ncu sampling slot (-s 5 -c 1) toward gemm_kernel.
extern "C" void kernel_launch(void* const* d_in, const int* in_sizes, int n_in,
                              void* d_out, int out_size)
{
    const float* X1    = (const float*)d_in[0];
    const float* X2    = (const float*)d_in[1];
    const int*   rows1 = (const int*)  d_in[2];
    const int*   cols1 = (const int*)  d_in[3];
    const float* vals1 = (const float*)d_in[4];
    const int*   rows2 = (const int*)  d_in[5];
    const int*   cols2 = (const int*)  d_in[6];
    const float* vals2 = (const float*)d_in[7];
    const float* W1    = (const float*)d_in[8];
    const float* b1    = (const float*)d_in[9];
    const float* W2    = (const float*)d_in[10];
    const float* b2    = (const float*)d_in[11];
    float* out = (float*)d_out;
    const int E = in_sizes[2];

    float *Hp = nullptr, *Zp = nullptr;
    int   *Cp = nullptr;
    cudaGetSymbolAddress((void**)&Hp, g_H);
    cudaGetSymbolAddress((void**)&Zp, g_Z);
    cudaGetSymbolAddress((void**)&Cp, g_counts);

    const int gemmBlocks = (N_TOT + TM - 1) / TM;     // 782
    const int edgeBlocks = (2 * E + 255) / 256;
    const int spmmBlocks = (N_TOT * 32 + 255) / 256;

    // CSR prefix (counts/offsets) for both graphs
    cudaMemsetAsync(Cp, 0, N_TOT * sizeof(int));
    hist_kernel<<<edgeBlocks, 256>>>(rows1, rows2, E);
    scan_block_kernel<<<SCAN_BLOCKS, 1024>>>();
    add_sums_kernel<<<SCAN_BLOCKS, 1024>>>();

    // H = [X1;X2] @ W1  (A split across the two input tensors)
    gemm_kernel<<<gemmBlocks, 256>>>(X1, X2, N_NODES, IN_DIM, W1, IN_DIM, Hp);
    // CSR edge scatter (needed only by spmm)
    scatter_kernel<<<edgeBlocks, 256>>>(rows1, cols1, vals1, rows2, cols2, vals2, E);
    // Z = selu(A @ H + b1), both graphs
    spmm_kernel<<<spmmBlocks, 256>>>(Hp, b1, Zp, 0);
    // H = Z @ W2  (Z is one contiguous buffer: Mhalf = N_TOT, no split)
    gemm_kernel<<<gemmBlocks, 256>>>(Zp, Zp, N_TOT, HID, W2, HID, Hp);
    // out = l2norm(A @ H + b2), both graphs
    spmm_kernel<<<spmmBlocks, 256>>>(Hp, b2, out, 1);
}

// round 16
// speedup vs baseline: 1.1878x; 1.1811x over previous
#include <cuda_runtime.h>
#include <cuda_fp16.h>
#include <math.h>

#define N_NODES 100000
#define N_TOT   200000            // both graphs fused
#define N_EDGES_MAX 1300000
#define IN_DIM 256
#define HID 64
#define SCAN_BLOCKS ((N_TOT + 1023) / 1024)   // 196
#define TM 128                    // GEMM block-tile rows
#define KC 16                     // GEMM k-chunk

// ---------------- packed f32x2 helpers (Blackwell dual-pumped fp32 FMA) ----------------
typedef unsigned long long f32x2_t;

__device__ __forceinline__ f32x2_t ffma2(f32x2_t a, f32x2_t b, f32x2_t c) {
    f32x2_t d;
    asm("fma.rn.f32x2 %0, %1, %2, %3;" : "=l"(d) : "l"(a), "l"(b), "l"(c));
    return d;
}
__device__ __forceinline__ f32x2_t dup2(float x) {
    f32x2_t d;
    asm("mov.b64 %0, {%1, %1};" : "=l"(d) : "f"(x));
    return d;
}
__device__ __forceinline__ float2 unpack2(f32x2_t d) {
    float2 r;
    asm("mov.b64 {%0, %1}, %2;" : "=f"(r.x), "=f"(r.y) : "l"(d));
    return r;
}

// ---------------- scratch (static device globals: no allocation allowed) ----------------
__device__ int    g_counts[N_TOT];
__device__ int    g_offsets[N_TOT];
__device__ int    g_cursor[N_TOT];
__device__ float2 g_edge[2 * N_EDGES_MAX];     // CSR-ordered (globalized col, val)
__device__ int    g_blocksums[256];
__device__ float  g_H[(size_t)N_TOT * HID];    // GEMM output (stored fp16; reinterpreted)
__device__ float  g_Z[(size_t)N_TOT * HID];    // activated layer-1 output (fp32)

// ---------------- CSR build: counting sort of edges by destination row ----------------
__global__ void hist_kernel(const int* __restrict__ rows1, const int* __restrict__ rows2, int E) {
    int i = blockIdx.x * blockDim.x + threadIdx.x;
    if (i < 2 * E) {
        int r = (i < E) ? rows1[i] : (N_NODES + rows2[i - E]);
        atomicAdd(&g_counts[r], 1);
    }
}

__global__ void scan_block_kernel() {
    __shared__ int sh[1024];
    int i = blockIdx.x * 1024 + threadIdx.x;
    int v = (i < N_TOT) ? g_counts[i] : 0;
    sh[threadIdx.x] = v;
    __syncthreads();
    #pragma unroll
    for (int d = 1; d < 1024; d <<= 1) {
        int t = 0;
        if ((int)threadIdx.x >= d) t = sh[threadIdx.x - d];
        __syncthreads();
        if ((int)threadIdx.x >= d) sh[threadIdx.x] += t;
        __syncthreads();
    }
    if (i < N_TOT) g_offsets[i] = sh[threadIdx.x] - v;   // exclusive within block
    if (threadIdx.x == 1023) g_blocksums[blockIdx.x] = sh[1023];
}

// Fused: per-block parallel reduction of predecessor block sums + offset fixup.
__global__ void add_sums_kernel() {
    __shared__ int sh[1024];
    int b = blockIdx.x;
    sh[threadIdx.x] = ((int)threadIdx.x < b) ? g_blocksums[threadIdx.x] : 0;  // b <= 195 < 1024
    __syncthreads();
    #pragma unroll
    for (int d = 512; d > 0; d >>= 1) {
        if ((int)threadIdx.x < d) sh[threadIdx.x] += sh[threadIdx.x + d];
        __syncthreads();
    }
    int base = sh[0];
    int i = b * 1024 + threadIdx.x;
    if (i < N_TOT) {
        int o = g_offsets[i] + base;
        g_offsets[i] = o;
        g_cursor[i]  = o;
    }
}

// Scatter edge PAYLOAD (globalized col, val) into CSR order.
__global__ void scatter_kernel(const int* __restrict__ rows1, const int* __restrict__ cols1,
                               const float* __restrict__ vals1,
                               const int* __restrict__ rows2, const int* __restrict__ cols2,
                               const float* __restrict__ vals2, int E) {
    int i = blockIdx.x * blockDim.x + threadIdx.x;
    if (i >= 2 * E) return;
    int r, c; float v;
    if (i < E) { r = rows1[i];            c = cols1[i];            v = vals1[i]; }
    else       { int j = i - E;
                 r = N_NODES + rows2[j];  c = N_NODES + cols2[j];  v = vals2[j]; }
    int p = atomicAdd(&g_cursor[r], 1);
    g_edge[p] = make_float2(__int_as_float(c), v);
}

// ---------------- dense GEMM: C[M,64](fp16) = A[M,lda](fp32) @ B[K,64](fp32) ----------------
// 128x64 block tile, 256 threads, 8x4 micro-tile as 4 row-pairs x 4 cols in packed
// f32x2 accumulators (accumulation fully fp32; only the OUTPUT store rounds to fp16,
// halving SPMM gather traffic). launch_bounds(256,3) -> 24 warps/SM for latency hiding
// (R6 profile: occ 23%, fma 48% = latency-bound).
__global__ __launch_bounds__(256, 3) void gemm_kernel(
    const float* __restrict__ A0, const float* __restrict__ A1, int Mhalf,
    int lda, const float* __restrict__ B, int K,
    __half* __restrict__ C)
{
    __shared__ float As[KC][TM + 2];   // [k][row]; row stride 520B (8B-aligned)
    __shared__ float Bs[KC][64];       // [k][col]

    const int t  = threadIdx.x;
    const int r0 = (t >> 4) * 8;       // 0..120, thread's 8 rows (4 pairs)
    const int c0 = (t & 15) * 4;       // 0..60, thread's 4 cols
    const int blockRow = blockIdx.x * TM;

    // A fragment sources: 128 rows x 16 k = 512 float4, 2 per thread.
    const float* srcA[2];
    int rowA[2], k4A[2];
    #pragma unroll
    for (int i = 0; i < 2; i++) {
        int idx4 = t + i * 256;
        int row = idx4 >> 2, k4 = idx4 & 3;
        rowA[i] = row; k4A[i] = k4;
        int gr = blockRow + row;
        if (gr > N_TOT - 1) gr = N_TOT - 1;          // clamp; stores are masked
        const float* base = (gr < Mhalf) ? (A0 + (size_t)gr * lda)
                                         : (A1 + (size_t)(gr - Mhalf) * lda);
        srcA[i] = base + k4 * 4;
    }
    // B fragment source: 16 x 64 = 256 float4, 1 per thread
    const int bkB = t >> 4, n4B = t & 15;
    const float* srcB = B + bkB * 64 + n4B * 4;

    f32x2_t acc[4][4];
    #pragma unroll
    for (int i = 0; i < 4; i++)
        #pragma unroll
        for (int j = 0; j < 4; j++) acc[i][j] = 0ull;  // (0.f, 0.f)

    const int nch = K / KC;
    float4 rA[2], rB;

    #pragma unroll
    for (int i = 0; i < 2; i++) rA[i] = *(const float4*)(srcA[i]);
    rB = *(const float4*)(srcB);

    for (int kc = 0; kc < nch; kc++) {
        // commit current chunk to shared ([k][row] transpose for A; conflict-free:
        // bank = 8*k4 + 2*x + row covers 0..31 across the warp)
        #pragma unroll
        for (int i = 0; i < 2; i++) {
            As[k4A[i] * 4 + 0][rowA[i]] = rA[i].x;
            As[k4A[i] * 4 + 1][rowA[i]] = rA[i].y;
            As[k4A[i] * 4 + 2][rowA[i]] = rA[i].z;
            As[k4A[i] * 4 + 3][rowA[i]] = rA[i].w;
        }
        *(float4*)&Bs[bkB][n4B * 4] = rB;
        __syncthreads();

        // prefetch next chunk (latency hidden behind the FMA block)
        if (kc + 1 < nch) {
            int off = (kc + 1) * KC;
            #pragma unroll
            for (int i = 0; i < 2; i++) rA[i] = *(const float4*)(srcA[i] + off);
            rB = *(const float4*)(srcB + off * 64);
        }

        #pragma unroll
        for (int k = 0; k < KC; k++) {
            // 4 row-pairs load directly as packed f32x2 (LDS.64, 2 unique addrs/warp)
            f32x2_t a0 = *(const f32x2_t*)&As[k][r0];
            f32x2_t a1 = *(const f32x2_t*)&As[k][r0 + 2];
            f32x2_t a2 = *(const f32x2_t*)&As[k][r0 + 4];
            f32x2_t a3 = *(const f32x2_t*)&As[k][r0 + 6];
            float4 bq = *(const float4*)&Bs[k][c0];
            float bv[4] = {bq.x, bq.y, bq.z, bq.w};
            #pragma unroll
            for (int j = 0; j < 4; j++) {
                f32x2_t bd = dup2(bv[j]);
                acc[0][j] = ffma2(a0, bd, acc[0][j]);
                acc[1][j] = ffma2(a1, bd, acc[1][j]);
                acc[2][j] = ffma2(a2, bd, acc[2][j]);
                acc[3][j] = ffma2(a3, bd, acc[3][j]);
            }
        }
        __syncthreads();
    }

    // epilogue: unpack row-pairs, round to fp16, one 8B store per row
    #pragma unroll
    for (int i = 0; i < 4; i++) {
        int gr = blockRow + r0 + 2 * i;
        float2 u[4];
        #pragma unroll
        for (int j = 0; j < 4; j++) u[j] = unpack2(acc[i][j]);
        if (gr < N_TOT) {
            union { __half2 h[2]; uint2 w; } cv;
            cv.h[0] = __floats2half2_rn(u[0].x, u[1].x);
            cv.h[1] = __floats2half2_rn(u[2].x, u[3].x);
            *(uint2*)(C + (size_t)gr * 64 + c0) = cv.w;   // byte off = gr*128 + 2*c0, 8B-aligned
        }
        if (gr + 1 < N_TOT) {
            union { __half2 h[2]; uint2 w; } cv;
            cv.h[0] = __floats2half2_rn(u[0].y, u[1].y);
            cv.h[1] = __floats2half2_rn(u[2].y, u[3].y);
            *(uint2*)(C + (size_t)(gr + 1) * 64 + c0) = cv.w;
        }
    }
}

// ---------------- SPMM (CSR gather of fp16 H, warp per row) + fused epilogue ----------------
// mode 0: out = selu(acc + bias)   mode 1: out = L2-normalize(acc + bias)
// H row = 64 fp16 = 128B = exactly one L2 line per gather (was two with fp32).
// Accumulation stays fp32. Unroll-8 front batch keeps 8 gathers in flight.
__global__ void spmm_kernel(const __half2* __restrict__ H2h, const float* __restrict__ bias,
                            float* __restrict__ outp, int mode)
{
    int w    = (blockIdx.x * blockDim.x + threadIdx.x) >> 5;
    int lane = threadIdx.x & 31;
    if (w >= N_TOT) return;

    int start = g_offsets[w];
    int cnt   = g_counts[w];

    float2 bv = ((const float2*)bias)[lane];
    float ax = bv.x, ay = bv.y;

    int j = 0;
    for (; j + 8 <= cnt; j += 8) {
        float2 e[8];
        #pragma unroll
        for (int u = 0; u < 8; u++) e[u] = g_edge[start + j + u];
        __half2 h[8];
        #pragma unroll
        for (int u = 0; u < 8; u++)
            h[u] = H2h[(size_t)__float_as_int(e[u].x) * 32 + lane];
        #pragma unroll
        for (int u = 0; u < 8; u++) {
            float2 hf = __half22float2(h[u]);
            ax = fmaf(e[u].y, hf.x, ax);
            ay = fmaf(e[u].y, hf.y, ay);
        }
    }
    for (; j + 4 <= cnt; j += 4) {
        float2 e[4];
        #pragma unroll
        for (int u = 0; u < 4; u++) e[u] = g_edge[start + j + u];
        __half2 h[4];
        #pragma unroll
        for (int u = 0; u < 4; u++)
            h[u] = H2h[(size_t)__float_as_int(e[u].x) * 32 + lane];
        #pragma unroll
        for (int u = 0; u < 4; u++) {
            float2 hf = __half22float2(h[u]);
            ax = fmaf(e[u].y, hf.x, ax);
            ay = fmaf(e[u].y, hf.y, ay);
        }
    }
    for (; j < cnt; j++) {
        float2 e = g_edge[start + j];
        float2 hf = __half22float2(H2h[(size_t)__float_as_int(e.x) * 32 + lane]);
        ax = fmaf(e.y, hf.x, ax);
        ay = fmaf(e.y, hf.y, ay);
    }

    if (mode == 0) {
        const float sc = 1.0507009873554805f;
        const float al = 1.6732632423543772f;
        float rx = ax > 0.f ? sc * ax : sc * al * (expf(ax) - 1.f);
        float ry = ay > 0.f ? sc * ay : sc * al * (expf(ay) - 1.f);
        ((float2*)outp)[(size_t)w * 32 + lane] = make_float2(rx, ry);
    } else {
        float ss = ax * ax + ay * ay;
        #pragma unroll
        for (int o = 16; o > 0; o >>= 1) ss += __shfl_xor_sync(0xffffffffu, ss, o);
        float inv = 1.f / fmaxf(sqrtf(ss), 1e-12f);
        ((float2*)outp)[(size_t)w * 32 + lane] = make_float2(ax * inv, ay * inv);
    }
}

// ---------------- launcher ----------------
// scatter is placed AFTER gemm1 (only spmm depends on it) to steer the fixed
// ncu sampling slot (-s 5 -c 1) toward gemm_kernel.
extern "C" void kernel_launch(void* const* d_in, const int* in_sizes, int n_in,
                              void* d_out, int out_size)
{
    const float* X1    = (const float*)d_in[0];
    const float* X2    = (const float*)d_in[1];
    const int*   rows1 = (const int*)  d_in[2];
    const int*   cols1 = (const int*)  d_in[3];
    const float* vals1 = (const float*)d_in[4];
    const int*   rows2 = (const int*)  d_in[5];
    const int*   cols2 = (const int*)  d_in[6];
    const float* vals2 = (const float*)d_in[7];
    const float* W1    = (const float*)d_in[8];
    const float* b1    = (const float*)d_in[9];
    const float* W2    = (const float*)d_in[10];
    const float* b2    = (const float*)d_in[11];
    float* out = (float*)d_out;
    const int E = in_sizes[2];

    float *Hp = nullptr, *Zp = nullptr;
    int   *Cp = nullptr;
    cudaGetSymbolAddress((void**)&Hp, g_H);
    cudaGetSymbolAddress((void**)&Zp, g_Z);
    cudaGetSymbolAddress((void**)&Cp, g_counts);
    __half*  Hh  = (__half*)Hp;
    __half2* Hh2 = (__half2*)Hp;

    const int gemmBlocks = (N_TOT + TM - 1) / TM;     // 1563
    const int edgeBlocks = (2 * E + 255) / 256;
    const int spmmBlocks = (N_TOT * 32 + 255) / 256;

    // CSR prefix (counts/offsets) for both graphs
    cudaMemsetAsync(Cp, 0, N_TOT * sizeof(int));
    hist_kernel<<<edgeBlocks, 256>>>(rows1, rows2, E);
    scan_block_kernel<<<SCAN_BLOCKS, 1024>>>();
    add_sums_kernel<<<SCAN_BLOCKS, 1024>>>();

    // H(fp16) = [X1;X2] @ W1  (A split across the two input tensors)
    gemm_kernel<<<gemmBlocks, 256>>>(X1, X2, N_NODES, IN_DIM, W1, IN_DIM, Hh);
    // CSR edge scatter (needed only by spmm)
    scatter_kernel<<<edgeBlocks, 256>>>(rows1, cols1, vals1, rows2, cols2, vals2, E);
    // Z(fp32) = selu(A @ H + b1), both graphs
    spmm_kernel<<<spmmBlocks, 256>>>(Hh2, b1, Zp, 0);
    // H(fp16) = Z @ W2  (Z is one contiguous buffer: Mhalf = N_TOT, no split)
    gemm_kernel<<<gemmBlocks, 256>>>(Zp, Zp, N_TOT, HID, W2, HID, Hh);
    // out = l2norm(A @ H + b2), both graphs
    spmm_kernel<<<spmmBlocks, 256>>>(Hh2, b2, out, 1);
}